// round 9
// baseline (speedup 1.0000x reference)
#include <cuda_runtime.h>
#include <cuda_fp16.h>

// PPO loss + GAE, B=4096 x T=2048 — single persistent fused kernel.
//
// Grid = 1024 CTAs x 128 threads, 4 rows per CTA (exactly 4096 rows).
// Residency: smem ~21KB -> cap 10 CTAs/SM; threads -> 16; regs (<=73 via
// __launch_bounds__(128,7)) -> >=7. Wave 1 needs max 7 CTAs/SM, so ALL
// CTAs are resident and the grid-wide spin sync is deadlock-free.
//
// Phase 1: one warp per row. Blocked affine suffix scan (CHUNK=8, 256
//          steps per warp-scan segment) of adv[t]=d[t]+c[t]*adv[t+1].
//          `values` is loaded COALESCED (stride-32 lane pattern, ~18 L1
//          wavefronts/segment vs 72 for the old strided scalar loads) and
//          transposed through a padded, bank-conflict-free smem tile.
//          Advantages staged in smem as fp16. Exact fp32->double
//          sum(adv), sum(adv^2); value_loss = mean(adv^2).
// Sync:    atomic arrive + volatile-load spin (no atomic-poll hammering).
// Phase 2: mean/rstd from global sums; clipped PPO surrogate + entropy,
//          using min(r*adv, clip(r)*adv) = (adv>0?min(r,1.2):max(r,0.8))*adv.
// Finish:  last CTA writes the 4 outputs and resets all device globals.
//
// Traffic: 96MB (phase 1) + 64MB (phase 2) = 160MB.

namespace {
constexpr int B = 4096;
constexpr int T = 2048;
constexpr long long NTOT = (long long)B * T;   // 8388608
constexpr float GAMMA = 0.99f;
constexpr float LAM   = 0.95f;
constexpr float GL    = GAMMA * LAM;
constexpr float CLIPP = 0.2f;
constexpr float EPSF  = 1e-9f;

constexpr int CHUNK = 8;                 // timesteps per lane per segment
constexpr int SEG   = 32 * CHUNK;        // 256 timesteps per warp scan
constexpr int NSEG  = T / SEG;           // 8

constexpr int GRID  = 1024;              // CTAs (all resident: 7/SM max)
constexpr int RPC   = 4;                 // rows per CTA (1024*4 = 4096)
constexpr int VTILE = 280;               // padded 257 -> 266, rounded up
}

__device__ double g_sum, g_sumsq, g_ppo, g_ent;   // zero-init; reset each replay
__device__ int    g_c1, g_c2;                      // phase counters

__device__ __forceinline__ int vpad(int p) { return p + (p >> 5); }

__global__ __launch_bounds__(128, 7) void ppo_fused_kernel(
    const float* __restrict__ rewards,
    const float* __restrict__ values,
    const float* __restrict__ masks,
    const float* __restrict__ old_p,
    const float* __restrict__ curr_p,
    float* __restrict__ out)
{
    __shared__ __half s_adv[RPC][T];     // 16 KB fp16 advantages
    __shared__ float  s_v[4][VTILE];     // 4.4 KB per-warp values transpose tile
    __shared__ double s_a[4], s_b[4];
    __shared__ float  sh_mean, sh_rstd;

    const int tid  = threadIdx.x;
    const int lane = tid & 31;
    const int wid  = tid >> 5;
    const unsigned FULL = 0xffffffffu;

    // ================= Phase 1: GAE -> smem fp16, moment sums =================
    float lsum = 0.f, lsq = 0.f;

    {
        const int row = blockIdx.x + GRID * wid;     // one warp per row

        const float* rr = rewards + (size_t)row * T;
        const float* vr = values  + (size_t)row * (T + 1);
        const float* mr = masks   + (size_t)row * T;
        __half*      ar = &s_adv[wid][0];

        float carry = 0.f;   // adv just past the current segment (adv[T]=0)

        for (int seg = NSEG - 1; seg >= 0; --seg) {
            const int sb   = seg * SEG;
            const int base = sb + lane * CHUNK;

            // ---- values: coalesced stride-32 loads -> padded smem tile ----
            // write p = k*32+lane: addr = k*33+lane -> banks (k+lane)%32, no conflict
            #pragma unroll
            for (int k = 0; k < CHUNK; ++k) {
                const int p = k * 32 + lane;
                s_v[wid][vpad(p)] = __ldcs(vr + sb + p);
            }
            if (lane == 0) s_v[wid][vpad(SEG)] = __ldcs(vr + sb + SEG);
            __syncwarp();

            // ---- rewards/masks: float4 coalesced ----
            const float4 ra = __ldcs((const float4*)(rr + base));
            const float4 rb = __ldcs((const float4*)(rr + base + 4));
            const float4 ma = __ldcs((const float4*)(mr + base));
            const float4 mb = __ldcs((const float4*)(mr + base + 4));
            const float r_[CHUNK] = {ra.x, ra.y, ra.z, ra.w, rb.x, rb.y, rb.z, rb.w};
            const float m_[CHUNK] = {ma.x, ma.y, ma.z, ma.w, mb.x, mb.y, mb.z, mb.w};

            // ---- per-step affine coefficients ----
            // read p = lane*8+j: addr = lane*8 + lane/4 + j -> 32 distinct banks
            float c[CHUNK], d[CHUNK];
            {
                const int rb_ = lane * CHUNK;
                float vj = s_v[wid][vpad(rb_)];
                #pragma unroll
                for (int j = 0; j < CHUNK; ++j) {
                    const float vn = s_v[wid][vpad(rb_ + j + 1)];
                    c[j] = GL * m_[j];
                    d[j] = fmaf(GAMMA * vn, m_[j], r_[j]) - vj;
                    vj = vn;
                }
            }
            __syncwarp();   // tile reads done before next segment's stores

            // ---- local suffix composition over this lane's 8 steps ----
            float C = c[CHUNK - 1], D = d[CHUNK - 1];
            #pragma unroll
            for (int j = CHUNK - 2; j >= 0; --j) {
                D = fmaf(c[j], D, d[j]);
                C = c[j] * C;
            }

            // ---- warp inclusive suffix scan of the 32 per-lane maps ----
            #pragma unroll
            for (int off = 1; off < 32; off <<= 1) {
                const float C2 = __shfl_down_sync(FULL, C, off);
                const float D2 = __shfl_down_sync(FULL, D, off);
                if (lane + off < 32) {
                    D = fmaf(C, D2, D);
                    C = C * C2;
                }
            }

            // x = adv at my chunk's end+1 (maps of lanes > me applied to carry)
            const float Cx = __shfl_down_sync(FULL, C, 1);
            const float Dx = __shfl_down_sync(FULL, D, 1);
            float x = (lane == 31) ? carry : fmaf(Cx, carry, Dx);

            float a[CHUNK];
            #pragma unroll
            for (int j = CHUNK - 1; j >= 0; --j) {
                a[j] = fmaf(c[j], x, d[j]);
                x = a[j];
            }
            carry = __shfl_sync(FULL, x, 0);

            // pack 8 fp16 and store 16B to smem
            const __half2 h0 = __floats2half2_rn(a[0], a[1]);
            const __half2 h1 = __floats2half2_rn(a[2], a[3]);
            const __half2 h2 = __floats2half2_rn(a[4], a[5]);
            const __half2 h3 = __floats2half2_rn(a[6], a[7]);
            uint4 pk;
            pk.x = *(const unsigned*)&h0;  pk.y = *(const unsigned*)&h1;
            pk.z = *(const unsigned*)&h2;  pk.w = *(const unsigned*)&h3;
            *(uint4*)(ar + base) = pk;

            #pragma unroll
            for (int j = 0; j < CHUNK; ++j) {
                lsum += a[j];
                lsq = fmaf(a[j], a[j], lsq);
            }
        }
    }

    // CTA reduce of the moments
    #pragma unroll
    for (int off = 16; off; off >>= 1) {
        lsum += __shfl_down_sync(FULL, lsum, off);
        lsq  += __shfl_down_sync(FULL, lsq,  off);
    }
    if (lane == 0) { s_a[wid] = (double)lsum; s_b[wid] = (double)lsq; }
    __syncthreads();
    if (tid == 0) {
        double bs = 0.0, bq = 0.0;
        #pragma unroll
        for (int i = 0; i < 4; ++i) { bs += s_a[i]; bq += s_b[i]; }
        atomicAdd(&g_sum,   bs);
        atomicAdd(&g_sumsq, bq);
        __threadfence();
        atomicAdd(&g_c1, 1);
        // volatile-load spin (no atomic hammering); all CTAs resident: safe
        while (*(volatile int*)&g_c1 < GRID) __nanosleep(32);
        const double n    = (double)NTOT;
        const double mean = g_sum / n;
        const double var  = (g_sumsq - g_sum * g_sum / n) / (n - 1.0);  // ddof=1
        sh_mean = (float)mean;
        sh_rstd = (float)(1.0 / (sqrt(var) + (double)EPSF));
    }
    __syncthreads();

    // ================= Phase 2: PPO surrogate + entropy =================
    const float mean = sh_mean, rstd = sh_rstd;
    float ppo = 0.f, ent = 0.f;

    #pragma unroll
    for (int i = 0; i < RPC; ++i) {
        const int row = blockIdx.x + GRID * i;

        const float4* o4 = (const float4*)(old_p  + (size_t)row * T);
        const float4* c4 = (const float4*)(curr_p + (size_t)row * T);
        const __half* ar = &s_adv[i][0];

        #pragma unroll
        for (int cch = 0; cch < 4; ++cch) {
            const int idx = cch * 128 + tid;     // float4 index within row
            const float4 o  = __ldcs(o4 + idx);
            const float4 cc = __ldcs(c4 + idx);
            const uint2 hh = *(const uint2*)(ar + idx * 4);
            const __half2 ha = *(const __half2*)&hh.x;
            const __half2 hb = *(const __half2*)&hh.y;
            const float2 fa = __half22float2(ha);
            const float2 fb = __half22float2(hb);

            const float av[4] = {fa.x, fa.y, fb.x, fb.y};
            const float* ov = (const float*)&o;
            const float* cv = (const float*)&cc;
            #pragma unroll
            for (int k = 0; k < 4; ++k) {
                const float ratio = __fdividef(cv[k], ov[k] + EPSF);
                const float adv   = (av[k] - mean) * rstd;
                // min(r*adv, clip(r)*adv) = (adv>0 ? min(r,1+c) : max(r,1-c)) * adv
                const float rlo = fminf(ratio, 1.f + CLIPP);
                const float rhi = fmaxf(ratio, 1.f - CLIPP);
                ppo = fmaf((adv > 0.f) ? rlo : rhi, adv, ppo);
                ent = fmaf(cv[k], __logf(cv[k] + EPSF), ent);
            }
        }
    }

    #pragma unroll
    for (int off = 16; off; off >>= 1) {
        ppo += __shfl_down_sync(FULL, ppo, off);
        ent += __shfl_down_sync(FULL, ent, off);
    }
    __syncthreads();   // s_a/s_b reuse
    if (lane == 0) { s_a[wid] = (double)ppo; s_b[wid] = (double)ent; }
    __syncthreads();

    if (tid == 0) {
        double bp = 0.0, be = 0.0;
        #pragma unroll
        for (int i = 0; i < 4; ++i) { bp += s_a[i]; be += s_b[i]; }
        atomicAdd(&g_ppo, bp);
        atomicAdd(&g_ent, be);
        __threadfence();
        const int done = atomicAdd(&g_c2, 1);
        if (done == GRID - 1) {
            // last CTA: finalize output, reset state for the next replay
            const double n   = (double)NTOT;
            const double pl  = -(g_ppo / n);
            const double vls = 0.5  * (g_sumsq / n);   // value_loss = mean(adv^2)
            const double el  = -0.01 * (g_ent / n);
            out[0] = (float)(pl + vls + el);
            out[1] = (float)pl;
            out[2] = (float)vls;
            out[3] = (float)el;
            g_sum = 0.0; g_sumsq = 0.0; g_ppo = 0.0; g_ent = 0.0;
            g_c1 = 0; g_c2 = 0;
            __threadfence();
        }
    }
}

extern "C" void kernel_launch(void* const* d_in, const int* in_sizes, int n_in,
                              void* d_out, int out_size)
{
    // `values` has the unique size B*(T+1); everything else keeps metadata
    // order: rewards, ref_probs (unused), old_probs, curr_probs, masks.
    int vi = 1;
    for (int i = 0; i < n_in; ++i)
        if (in_sizes[i] == B * (T + 1)) { vi = i; break; }

    const float* others[8];
    int k = 0;
    for (int i = 0; i < n_in; ++i)
        if (i != vi) others[k++] = (const float*)d_in[i];

    const float* rewards = others[0];
    const float* old_p   = others[2];
    const float* curr_p  = others[3];
    const float* masks   = others[4];
    const float* values  = (const float*)d_in[vi];

    ppo_fused_kernel<<<GRID, 128>>>(rewards, values, masks, old_p, curr_p,
                                    (float*)d_out);
}